// round 2
// baseline (speedup 1.0000x reference)
#include <cuda_runtime.h>

#define B_ 32
#define T_ 2048
#define F_ 128
#define U_ 128
#define G_ 384   /* 3U */
#define C_ 11
#define R_ (B_*T_)  /* 65536 rows */

// ---------------------------------------------------------------------------
// Scratch (device globals: no runtime allocation allowed)
// ---------------------------------------------------------------------------
__device__ float g_xg[2][R_ * G_];      // input projections per direction
__device__ float g_hs[R_ * 2 * U_];     // concat hidden states [b*T+t][256]

// ---------------------------------------------------------------------------
// Packed fp32x2 helpers
// ---------------------------------------------------------------------------
__device__ __forceinline__ unsigned long long ffma2(unsigned long long a,
                                                    unsigned long long b,
                                                    unsigned long long c) {
    unsigned long long d;
    asm("fma.rn.f32x2 %0, %1, %2, %3;" : "=l"(d) : "l"(a), "l"(b), "l"(c));
    return d;
}
__device__ __forceinline__ unsigned long long add2(unsigned long long a,
                                                   unsigned long long b) {
    unsigned long long d;
    asm("add.rn.f32x2 %0, %1, %2;" : "=l"(d) : "l"(a), "l"(b));
    return d;
}
__device__ __forceinline__ unsigned long long pack2(float x, float y) {
    unsigned long long r;
    asm("mov.b64 %0, {%1, %2};" : "=l"(r) : "f"(x), "f"(y));
    return r;
}
__device__ __forceinline__ float sum2(unsigned long long v) {
    float lo, hi;
    asm("mov.b64 {%0, %1}, %2;" : "=f"(lo), "=f"(hi) : "l"(v));
    return lo + hi;
}
__device__ __forceinline__ float sigf(float x) {
    return __fdividef(1.f, 1.f + __expf(-x));
}

// ---------------------------------------------------------------------------
// Phase 1: xg[dir] = x @ W[dir] + b[dir][0]
// C[65536,384] = A[65536,128] * W[128,384].
// BM=128, BN=128, BK=16, 256 threads, 8x8 micro-tile, packed f32x2 FMAs.
// A stored in smem K-major *duplicated* (each a value twice, as a u64) so the
// packed multiplier needs no replication MOVs.
// ---------------------------------------------------------------------------
__global__ __launch_bounds__(256) void proj_kernel(
    const float* __restrict__ x,
    const float* __restrict__ Wf, const float* __restrict__ bf,
    const float* __restrict__ Wb, const float* __restrict__ bb)
{
    const int dir = blockIdx.z;
    const float* __restrict__ W    = dir ? Wb : Wf;
    const float* __restrict__ bias = dir ? bb : bf;   // row 0 of [2,384]
    float* __restrict__ Cout = g_xg[dir];

    const int r0 = blockIdx.x * 128;
    const int c0 = blockIdx.y * 128;

    __shared__ __align__(16) unsigned long long As2[16 * 128]; // [k][i] dup'd -> 16KB
    __shared__ __align__(16) float Bs[16 * 128];               // [k][j]     ->  8KB

    const int tid = threadIdx.x;
    const int tx  = tid & 15;        // j group (8 cols)
    const int ty  = tid >> 4;        // i group (8 rows)
    const int i0  = ty * 8;
    const int j0  = tx * 8;

    unsigned long long acc[8][4];    // [i][j-pair]
    #pragma unroll
    for (int i = 0; i < 8; i++)
        #pragma unroll
        for (int jp = 0; jp < 4; jp++) acc[i][jp] = 0ull;

    for (int k0 = 0; k0 < F_; k0 += 16) {
        // A tile: 128 rows x 16 k  (512 float4); store duplicated K-major
        #pragma unroll
        for (int q = 0; q < 2; q++) {
            int idx = tid + 256 * q;
            int i   = idx >> 2;
            int k4  = (idx & 3) * 4;
            float4 v = *(const float4*)(x + (size_t)(r0 + i) * F_ + k0 + k4);
            As2[(k4 + 0) * 128 + i] = pack2(v.x, v.x);
            As2[(k4 + 1) * 128 + i] = pack2(v.y, v.y);
            As2[(k4 + 2) * 128 + i] = pack2(v.z, v.z);
            As2[(k4 + 3) * 128 + i] = pack2(v.w, v.w);
        }
        // B tile: 16 k x 128 cols (512 float4)
        #pragma unroll
        for (int q = 0; q < 2; q++) {
            int idx = tid + 256 * q;
            int kk  = idx >> 5;
            int j4  = (idx & 31) * 4;
            *(float4*)(Bs + kk * 128 + j4) =
                *(const float4*)(W + (size_t)(k0 + kk) * G_ + c0 + j4);
        }
        __syncthreads();

        #pragma unroll
        for (int kk = 0; kk < 16; kk++) {
            const ulonglong2* ap = (const ulonglong2*)(As2 + kk * 128 + i0);
            const ulonglong2* bp = (const ulonglong2*)(Bs + kk * 128 + j0);
            ulonglong2 a01 = ap[0], a23 = ap[1], a45 = ap[2], a67 = ap[3];
            ulonglong2 b01 = bp[0], b23 = bp[1];
            unsigned long long av[8] = {a01.x, a01.y, a23.x, a23.y,
                                        a45.x, a45.y, a67.x, a67.y};
            unsigned long long bv[4] = {b01.x, b01.y, b23.x, b23.y};
            #pragma unroll
            for (int i = 0; i < 8; i++) {
                acc[i][0] = ffma2(av[i], bv[0], acc[i][0]);
                acc[i][1] = ffma2(av[i], bv[1], acc[i][1]);
                acc[i][2] = ffma2(av[i], bv[2], acc[i][2]);
                acc[i][3] = ffma2(av[i], bv[3], acc[i][3]);
            }
        }
        __syncthreads();
    }

    // epilogue: add bias, store
    float bcol[8];
    #pragma unroll
    for (int j = 0; j < 8; j++) bcol[j] = bias[c0 + j0 + j];

    #pragma unroll
    for (int i = 0; i < 8; i++) {
        float v[8];
        #pragma unroll
        for (int jp = 0; jp < 4; jp++) {
            float lo, hi;
            asm("mov.b64 {%0, %1}, %2;" : "=f"(lo), "=f"(hi) : "l"(acc[i][jp]));
            v[2 * jp]     = lo + bcol[2 * jp];
            v[2 * jp + 1] = hi + bcol[2 * jp + 1];
        }
        float* op = Cout + (size_t)(r0 + i0 + i) * G_ + c0 + j0;
        *(float4*)(op)     = make_float4(v[0], v[1], v[2], v[3]);
        *(float4*)(op + 4) = make_float4(v[4], v[5], v[6], v[7]);
    }
}

// ---------------------------------------------------------------------------
// Phase 2: GRU recurrence. One persistent block per (batch, direction).
// 256 threads. Lane pair (2u, 2u+1) owns hidden unit u; the pair splits the
// K dimension (half = t&1 -> k in [64*half, 64*half+64)). Each thread holds
// all three gate columns (z,r,h) for its K-half in registers (96 packed u64).
// Partial dot products combined with one shfl.xor(1); activation computed
// redundantly by both lanes (bitwise identical). One barrier per step via
// double-buffered h in smem.
// ---------------------------------------------------------------------------
__global__ __launch_bounds__(256, 1) void gru_kernel(
    const float* __restrict__ Uf, const float* __restrict__ bf,
    const float* __restrict__ Ub, const float* __restrict__ bb)
{
    const int b    = blockIdx.x;
    const int dir  = blockIdx.y;
    const int tidx = threadIdx.x;
    const int u    = tidx >> 1;       // unit 0..127
    const int half = tidx & 1;        // K-half

    const float* __restrict__ Um   = dir ? Ub : Uf;
    const float* __restrict__ bias = dir ? bb : bf;
    const float* __restrict__ xg   = g_xg[dir] + (size_t)b * T_ * G_;
    float* __restrict__ hout = g_hs + (size_t)b * T_ * (2 * U_) + (dir ? U_ : 0);

    const int cz = u, cr = u + U_, ch = u + 2 * U_;
    const float bz = bias[G_ + cz];
    const float br = bias[G_ + cr];
    const float bh = bias[G_ + ch];

    // Gate columns for this K-half, packed by k-pairs.
    unsigned long long uz[32], ur[32], uh[32];
    const int k0 = half * 64;
    #pragma unroll
    for (int q = 0; q < 32; q++) {
        const int k = k0 + 2 * q;
        uz[q] = pack2(Um[(size_t)k * G_ + cz], Um[(size_t)(k + 1) * G_ + cz]);
        ur[q] = pack2(Um[(size_t)k * G_ + cr], Um[(size_t)(k + 1) * G_ + cr]);
        uh[q] = pack2(Um[(size_t)k * G_ + ch], Um[(size_t)(k + 1) * G_ + ch]);
    }

    __shared__ __align__(16) float hbuf[2][U_];
    if (tidx < U_) { hbuf[0][tidx] = 0.f; hbuf[1][tidx] = 0.f; }
    __syncthreads();

    const int stepd = dir ? -1 : 1;
    int t = dir ? (T_ - 1) : 0;
    float hprev = 0.f;

    float xz = xg[(size_t)t * G_ + cz];
    float xr = xg[(size_t)t * G_ + cr];
    float xh = xg[(size_t)t * G_ + ch];

    int p = 0;
    for (int s = 0; s < T_; s++) {
        const int tn  = t + stepd;
        const int tcl = min(max(tn, 0), T_ - 1);
        // Prefetch next timestep's input projections (hidden under the dot).
        const float nxz = xg[(size_t)tcl * G_ + cz];
        const float nxr = xg[(size_t)tcl * G_ + cr];
        const float nxh = xg[(size_t)tcl * G_ + ch];

        // Partial dots over this thread's K-half (6 independent FMA chains).
        const ulonglong2* hp = (const ulonglong2*)(hbuf[p] + (half << 6));
        unsigned long long az0 = 0ull, az1 = 0ull;
        unsigned long long ar0 = 0ull, ar1 = 0ull;
        unsigned long long ah0 = 0ull, ah1 = 0ull;
        #pragma unroll
        for (int q = 0; q < 8; q++) {
            const ulonglong2 hA = hp[2 * q];
            const ulonglong2 hB = hp[2 * q + 1];
            az0 = ffma2(hA.x, uz[4 * q + 0], az0);
            ar0 = ffma2(hA.x, ur[4 * q + 0], ar0);
            ah0 = ffma2(hA.x, uh[4 * q + 0], ah0);
            az1 = ffma2(hA.y, uz[4 * q + 1], az1);
            ar1 = ffma2(hA.y, ur[4 * q + 1], ar1);
            ah1 = ffma2(hA.y, uh[4 * q + 1], ah1);
            az0 = ffma2(hB.x, uz[4 * q + 2], az0);
            ar0 = ffma2(hB.x, ur[4 * q + 2], ar0);
            ah0 = ffma2(hB.x, uh[4 * q + 2], ah0);
            az1 = ffma2(hB.y, uz[4 * q + 3], az1);
            ar1 = ffma2(hB.y, ur[4 * q + 3], ar1);
            ah1 = ffma2(hB.y, uh[4 * q + 3], ah1);
        }
        float pz = sum2(add2(az0, az1));
        float pr = sum2(add2(ar0, ar1));
        float ph = sum2(add2(ah0, ah1));

        // Combine with partner lane; both lanes end with identical full sums.
        pz += __shfl_xor_sync(0xffffffffu, pz, 1);
        pr += __shfl_xor_sync(0xffffffffu, pr, 1);
        ph += __shfl_xor_sync(0xffffffffu, ph, 1);

        const float z  = sigf(xz + pz + bz);
        const float r  = sigf(xr + pr + br);
        const float hh = fmaxf(xh + r * (ph + bh), 0.f);
        const float hn = z * hprev + (1.f - z) * hh;
        hprev = hn;

        if (half == 0) hbuf[p ^ 1][u] = hn;         // even lane: next-step h
        else           hout[(size_t)t * (2 * U_) + u] = hn;  // odd lane: output
        __syncthreads();

        p ^= 1;
        t = tn;
        xz = nxz; xr = nxr; xh = nxh;
    }
}

// ---------------------------------------------------------------------------
// Phase 3: logits = h_cat @ Wd + bd ; softmax over C. One warp per (b,t) row.
// ---------------------------------------------------------------------------
__global__ __launch_bounds__(128) void dense_kernel(
    const float* __restrict__ Wd, const float* __restrict__ bd,
    float* __restrict__ out)
{
    __shared__ float wds[2 * U_ * C_];
    __shared__ float bds[C_];
    const int tid = threadIdx.x;
    for (int i = tid; i < 2 * U_ * C_; i += 128) wds[i] = Wd[i];
    if (tid < C_) bds[tid] = bd[tid];
    __syncthreads();

    const int w = tid >> 5;
    const int l = tid & 31;
    const size_t row = (size_t)blockIdx.x * 4 + w;

    const float* __restrict__ h = g_hs + row * (2 * U_);
    float hv[8];
    #pragma unroll
    for (int q = 0; q < 8; q++) hv[q] = h[l + 32 * q];

    float logit[C_];
    #pragma unroll
    for (int c = 0; c < C_; c++) {
        float a = 0.f;
        #pragma unroll
        for (int q = 0; q < 8; q++) a += hv[q] * wds[(l + 32 * q) * C_ + c];
        logit[c] = a;
    }
    #pragma unroll
    for (int c = 0; c < C_; c++) {
        #pragma unroll
        for (int off = 16; off; off >>= 1)
            logit[c] += __shfl_xor_sync(0xffffffffu, logit[c], off);
        logit[c] += bds[c];
    }

    float m = logit[0];
    #pragma unroll
    for (int c = 1; c < C_; c++) m = fmaxf(m, logit[c]);
    float e[C_], ssum = 0.f;
    #pragma unroll
    for (int c = 0; c < C_; c++) { e[c] = __expf(logit[c] - m); ssum += e[c]; }
    const float inv = __fdividef(1.f, ssum);
    if (l == 0) {
        #pragma unroll
        for (int c = 0; c < C_; c++) out[row * C_ + c] = e[c] * inv;
    }
}

// ---------------------------------------------------------------------------
extern "C" void kernel_launch(void* const* d_in, const int* in_sizes, int n_in,
                              void* d_out, int out_size)
{
    const float* x  = (const float*)d_in[0];
    const float* Wf = (const float*)d_in[1];
    const float* Uf = (const float*)d_in[2];
    const float* bf = (const float*)d_in[3];
    const float* Wb = (const float*)d_in[4];
    const float* Ub = (const float*)d_in[5];
    const float* bb = (const float*)d_in[6];
    const float* Wd = (const float*)d_in[7];
    const float* bd = (const float*)d_in[8];
    float* out = (float*)d_out;

    proj_kernel<<<dim3(R_ / 128, G_ / 128, 2), 256>>>(x, Wf, bf, Wb, bb);
    gru_kernel<<<dim3(B_, 2), 256>>>(Uf, bf, Ub, bb);
    dense_kernel<<<R_ / 4, 128>>>(Wd, bd, out);
}